// round 16
// baseline (speedup 1.0000x reference)
#include <cuda_runtime.h>
#include <cuda_bf16.h>
#include <cstdint>
#include <math.h>

// Problem dims (fixed by the dataset)
#define T_STEPS 512
#define B_SZ    64
#define D_SZ    256
#define H_SZ    256
#define ALPHA   0.9f

#define N_SCAN_CTAS   64
#define N_HELPERS     84
#define N_TILES       512   // preds: 256 bm x 2 bn, tiles of 128x128

__device__ float g_xw[(size_t)T_STEPS * B_SZ * H_SZ];
__device__ int   g_stepcnt[T_STEPS];   // #scan CTAs that completed step s (odd only)

// ---- f32x2 helpers (sm_103a packed fp32 FMA) --------------------------------
__device__ __forceinline__ unsigned long long pk2(float lo, float hi) {
    unsigned long long r;
    asm("mov.b64 %0, {%1, %2};" : "=l"(r) : "f"(lo), "f"(hi));
    return r;
}
__device__ __forceinline__ unsigned long long dup2(float a) {
    unsigned long long r;
    asm("mov.b64 %0, {%1, %1};" : "=l"(r) : "f"(a));
    return r;
}
__device__ __forceinline__ void fma2(unsigned long long& acc,
                                     unsigned long long a, unsigned long long b) {
    asm("fma.rn.f32x2 %0, %1, %2, %0;" : "+l"(acc) : "l"(a), "l"(b));
}
__device__ __forceinline__ float2 unpk(unsigned long long v) {
    float lo, hi;
    asm("mov.b64 {%0, %1}, %2;" : "=f"(lo), "=f"(hi) : "l"(v));
    return make_float2(lo, hi);
}

// ---- release/acquire flag ops ----------------------------------------------
__device__ __forceinline__ int ld_acq(const int* p) {
    int v;
    asm volatile("ld.acquire.gpu.global.s32 %0, [%1];" : "=r"(v) : "l"(p) : "memory");
    return v;
}
__device__ __forceinline__ void red_rel_add(int* p, int v) {
    asm volatile("red.release.gpu.global.add.s32 [%0], %1;" :: "l"(p), "r"(v) : "memory");
}

// ---------------------------------------------------------------------------
// 128x128 GEMM tile, 256 threads (standalone xw kernel). BK=8, FFMA2.
// ---------------------------------------------------------------------------
__device__ __forceinline__ void gemm_tile256(
    const float* __restrict__ A, const float* __restrict__ Bm,
    const float* __restrict__ bias, float* __restrict__ C,
    int bm, int bn, float* As, float* Bs)
{
    const int K = 256, N = 256;
    const int tid = threadIdx.x;
    const int tx = tid & 15;
    const int ty = tid >> 4;

    const int a_m = tid >> 1;
    const int a_k = (tid & 1) * 4;
    const int b_k = tid >> 5;
    const int b_n = (tid & 31) * 4;

    const float* Ap = A + (size_t)(bm + a_m) * K + a_k;
    const float* Bp = Bm + (size_t)b_k * N + bn + b_n;

    float4 af = *(const float4*)Ap;
    float4 bf = *(const float4*)Bp;

    unsigned long long acc2[8][4];
#pragma unroll
    for (int i = 0; i < 8; i++)
#pragma unroll
        for (int j = 0; j < 4; j++) acc2[i][j] = 0ull;

    int buf = 0;
    for (int kt = 0; kt < K; kt += 8) {
        As[(buf * 8 + a_k + 0) * 128 + a_m] = af.x;
        As[(buf * 8 + a_k + 1) * 128 + a_m] = af.y;
        As[(buf * 8 + a_k + 2) * 128 + a_m] = af.z;
        As[(buf * 8 + a_k + 3) * 128 + a_m] = af.w;
        *(float4*)&Bs[(buf * 8 + b_k) * 128 + b_n] = bf;
        __syncthreads();
        if (kt + 8 < K) {
            af = *(const float4*)(Ap + kt + 8);
            bf = *(const float4*)(Bp + (size_t)(kt + 8) * N);
        }
#pragma unroll
        for (int k = 0; k < 8; k++) {
            float4 a0 = *(const float4*)&As[(buf * 8 + k) * 128 + ty * 4];
            float4 a1 = *(const float4*)&As[(buf * 8 + k) * 128 + 64 + ty * 4];
            ulonglong2 bx0 = *(const ulonglong2*)&Bs[(buf * 8 + k) * 128 + tx * 4];
            ulonglong2 bx1 = *(const ulonglong2*)&Bs[(buf * 8 + k) * 128 + 64 + tx * 4];
            float av[8] = {a0.x, a0.y, a0.z, a0.w, a1.x, a1.y, a1.z, a1.w};
#pragma unroll
            for (int i = 0; i < 8; i++) {
                unsigned long long ad = dup2(av[i]);
                fma2(acc2[i][0], ad, bx0.x);
                fma2(acc2[i][1], ad, bx0.y);
                fma2(acc2[i][2], ad, bx1.x);
                fma2(acc2[i][3], ad, bx1.y);
            }
        }
        buf ^= 1;
    }

    float bv0[4], bv1[4];
#pragma unroll
    for (int j = 0; j < 4; j++) {
        bv0[j] = bias ? bias[bn + tx * 4 + j]      : 0.f;
        bv1[j] = bias ? bias[bn + 64 + tx * 4 + j] : 0.f;
    }

#pragma unroll
    for (int i = 0; i < 8; i++) {
        int r = bm + ((i < 4) ? (ty * 4 + i) : (64 + ty * 4 + (i - 4)));
        float2 p0 = unpk(acc2[i][0]), p1 = unpk(acc2[i][1]);
        float2 p2 = unpk(acc2[i][2]), p3 = unpk(acc2[i][3]);
        float4 o0, o1;
        o0.x = p0.x + bv0[0]; o0.y = p0.y + bv0[1];
        o0.z = p1.x + bv0[2]; o0.w = p1.y + bv0[3];
        o1.x = p2.x + bv1[0]; o1.y = p2.y + bv1[1];
        o1.z = p3.x + bv1[2]; o1.w = p3.y + bv1[3];
        *(float4*)&C[(size_t)r * N + bn + tx * 4]      = o0;
        *(float4*)&C[(size_t)r * N + bn + 64 + tx * 4] = o1;
    }
}

__global__ __launch_bounds__(256) void sgemm_k(
    const float* __restrict__ A, const float* __restrict__ Bm,
    const float* __restrict__ bias, float* __restrict__ C)
{
    __shared__ float As[2 * 8 * 128];
    __shared__ float Bs[2 * 8 * 128];
    gemm_tile256(A, Bm, bias, C, blockIdx.x * 128, blockIdx.y * 128, As, Bs);
}

// ---------------------------------------------------------------------------
// 128x128 GEMM tile, 512 threads (mega-kernel helpers). 8x4 outputs/thread.
// ---------------------------------------------------------------------------
__device__ __forceinline__ void gemm_tile512(
    const float* __restrict__ A, const float* __restrict__ Bm,
    const float* __restrict__ bias, float* __restrict__ C,
    int bm, int bn, float* As, float* Bs)
{
    const int K = 256, N = 256;
    const int tid = threadIdx.x;
    const int tx = tid & 31;        // 32 col groups of 4
    const int ty = tid >> 5;        // 16 row groups of 8

    const int a_m = tid >> 2;            // 0..127
    const int a_k = (tid & 3) * 2;       // 0,2,4,6
    const int b_k = tid >> 6;            // 0..7
    const int b_n = (tid & 63) * 2;      // 0..126

    const float* Ap = A + (size_t)(bm + a_m) * K + a_k;
    const float* Bp = Bm + (size_t)b_k * N + bn + b_n;

    float2 af = *(const float2*)Ap;
    float2 bf = *(const float2*)Bp;

    unsigned long long acc2[8][2];
#pragma unroll
    for (int i = 0; i < 8; i++) { acc2[i][0] = 0ull; acc2[i][1] = 0ull; }

    int buf = 0;
    for (int kt = 0; kt < K; kt += 8) {
        As[(buf * 8 + a_k + 0) * 128 + a_m] = af.x;
        As[(buf * 8 + a_k + 1) * 128 + a_m] = af.y;
        *(float2*)&Bs[(buf * 8 + b_k) * 128 + b_n] = bf;
        __syncthreads();
        if (kt + 8 < K) {
            af = *(const float2*)(Ap + kt + 8);
            bf = *(const float2*)(Bp + (size_t)(kt + 8) * N);
        }
#pragma unroll
        for (int k = 0; k < 8; k++) {
            float4 a0 = *(const float4*)&As[(buf * 8 + k) * 128 + ty * 8];
            float4 a1 = *(const float4*)&As[(buf * 8 + k) * 128 + ty * 8 + 4];
            ulonglong2 bx = *(const ulonglong2*)&Bs[(buf * 8 + k) * 128 + tx * 4];
            float av[8] = {a0.x, a0.y, a0.z, a0.w, a1.x, a1.y, a1.z, a1.w};
#pragma unroll
            for (int i = 0; i < 8; i++) {
                unsigned long long ad = dup2(av[i]);
                fma2(acc2[i][0], ad, bx.x);
                fma2(acc2[i][1], ad, bx.y);
            }
        }
        buf ^= 1;
    }

    float bv[4];
#pragma unroll
    for (int j = 0; j < 4; j++)
        bv[j] = bias ? bias[bn + tx * 4 + j] : 0.f;

#pragma unroll
    for (int i = 0; i < 8; i++) {
        int r = bm + ty * 8 + i;
        float2 p0 = unpk(acc2[i][0]), p1 = unpk(acc2[i][1]);
        float4 o;
        o.x = p0.x + bv[0]; o.y = p0.y + bv[1];
        o.z = p1.x + bv[2]; o.w = p1.y + bv[3];
        *(float4*)&C[(size_t)r * N + bn + tx * 4] = o;
    }
}

// ---------------------------------------------------------------------------
// Mega kernel, 512 threads. CTAs [0,64) = scan; [64,148) = preds helpers.
// Scan: col = tid>>1, kh = tid&1 (k-half). W per thread: 40 reg-pairs +
// 24 smem-pairs (12 ulonglong2). Partials combined via shfl.xor(1).
// 4 warps/SMSP for latency hiding; regs budgeted ~114 < 128 cap.
// ---------------------------------------------------------------------------
#define RP 40    // register W pairs per thread (80 k-rows of this thread's half)
#define SPAIR 24 // smem W pairs per thread (48 k-rows)
#define SVEC (SPAIR / 2)   // 12 ulonglong2

__global__ __launch_bounds__(512, 1) void mega_k(
    const float* __restrict__ spike0, const float* __restrict__ v0,
    const float* __restrict__ W_rec,  const float* __restrict__ W_out,
    float* __restrict__ spikes, float* __restrict__ preds,
    float* __restrict__ probs,  float* __restrict__ vT, float* __restrict__ sT,
    const float* __restrict__ xw)
{
    extern __shared__ __align__(16) unsigned char dynsm[];

    if (blockIdx.x >= N_SCAN_CTAS) {
        // ================= preds helper (512 threads) =================
        float* As = (float*)dynsm;
        float* Bs = As + 2 * 8 * 128;
        const int h = blockIdx.x - N_SCAN_CTAS;
        const float* spk1 = spikes + (size_t)B_SZ * H_SZ;   // spikes[1:]

        for (int i = h; i < N_TILES; i += N_HELPERS) {
            const int bm = i >> 1, bn = i & 1;
            const int need_step = 2 * bm + 1;     // odd; published by scan
            if (threadIdx.x == 0) {
                while (ld_acq(&g_stepcnt[need_step]) < N_SCAN_CTAS)
                    __nanosleep(512);
            }
            __syncthreads();                      // acquire visible block-wide
            gemm_tile512(spk1, W_out, nullptr, preds, bm * 128, bn * 128, As, Bs);
            __syncthreads();
        }
        return;
    }

    // ================= scan CTA (512 threads) =================
    ulonglong2* w4 = (ulonglong2*)dynsm;                  // [SVEC * 512]
    float* sbuf = (float*)(w4 + SVEC * 512);              // [2][256]

    const int tid = threadIdx.x;
    const int col = tid >> 1;        // output column 0..255
    const int kh  = tid & 1;         // k-half
    const int row = blockIdx.x;      // batch row
    const int kbase = kh * 128;

    // smem W: vec q covers k rows kbase + 2*RP + 4q .. +3, column col
#pragma unroll
    for (int q = 0; q < SVEC; q++) {
        const int kb = kbase + 2 * RP + 4 * q;
        ulonglong2 wv;
        wv.x = pk2(W_rec[(size_t)(kb + 0) * 256 + col], W_rec[(size_t)(kb + 1) * 256 + col]);
        wv.y = pk2(W_rec[(size_t)(kb + 2) * 256 + col], W_rec[(size_t)(kb + 3) * 256 + col]);
        w4[q * 512 + tid] = wv;
    }

    // register W pairs: k rows [kbase, kbase + 2*RP)
    unsigned long long wreg[RP];
#pragma unroll
    for (int j = 0; j < RP; j++)
        wreg[j] = pk2(W_rec[(size_t)(kbase + 2 * j) * 256 + col],
                      W_rec[(size_t)(kbase + 2 * j + 1) * 256 + col]);

    if (tid < 256) {
        const float s0 = spike0[row * 256 + tid];
        sbuf[tid] = s0;
        spikes[(size_t)row * 256 + tid] = s0;    // spikes[0] = spike0
    }

    float v = 0.f, prob = 0.f;
    if (kh == 0) {
        v = v0[row * 256 + col];
        prob = spike0[row * 256 + col];
    }

    const float* xwp = xw + (size_t)row * 256 + col;   // kh==0 only
    float xnext = (kh == 0) ? __ldg(xwp) : 0.f;

    __syncthreads();

    int cur = 0;
    for (int step = 0; step < T_STEPS; step++) {
        const float xval = xnext;
        if (kh == 0 && step + 1 < T_STEPS)
            xnext = __ldg(xwp + (size_t)(step + 1) * (B_SZ * H_SZ));

        unsigned long long a4[4] = {0ull, 0ull, 0ull, 0ull};

        // Register part: k in [kbase, kbase+80): 20 LDS.128 (s) + 40 FFMA2
        const ulonglong2* sp = (const ulonglong2*)&sbuf[cur * 256 + kbase];
#pragma unroll
        for (int q = 0; q < RP / 2; q++) {
            ulonglong2 sv = sp[q];
            fma2(a4[(2 * q) & 3],     wreg[2 * q],     sv.x);
            fma2(a4[(2 * q + 1) & 3], wreg[2 * q + 1], sv.y);
        }
        // Smem part: k in [kbase+80, kbase+128): 12 s-LDS.128 + 12 W-LDS.128
#pragma unroll
        for (int q = 0; q < SVEC; q++) {
            ulonglong2 sv = sp[RP / 2 + q];
            ulonglong2 wv = w4[q * 512 + tid];
            fma2(a4[0], wv.x, sv.x);
            fma2(a4[1], wv.y, sv.y);
        }

        float2 q0 = unpk(a4[0]), q1 = unpk(a4[1]), q2 = unpk(a4[2]), q3 = unpk(a4[3]);
        float acc = ((q0.x + q0.y) + (q1.x + q1.y)) + ((q2.x + q2.y) + (q3.x + q3.y));

        // Combine k-halves: partner is adjacent lane
        acc += __shfl_xor_sync(0xffffffffu, acc, 1);

        const int nxt = cur ^ 1;
        if (kh == 0) {
            v = ALPHA * v + xval + acc;
            prob = __fdividef(1.0f, 1.0f + __expf(-v));

            const size_t off = ((size_t)step * B_SZ + row) * 256 + col;
            probs[off] = prob;                        // probs[step]
            spikes[off + (size_t)B_SZ * 256] = prob;  // spikes[step+1]

            sbuf[nxt * 256 + col] = prob;
        }
        __syncthreads();   // new spikes visible; all reads of cur done
        if (tid == 0 && (step & 1)) red_rel_add(&g_stepcnt[step], 1);
        cur = nxt;
    }

    if (kh == 0) {
        vT[row * 256 + col] = v;
        sT[row * 256 + col] = prob;
    }
}

// ---------------------------------------------------------------------------
// Launch: memset flags -> sgemm(xw) -> mega(scan + preds helpers).
// ---------------------------------------------------------------------------
extern "C" void kernel_launch(void* const* d_in, const int* in_sizes, int n_in,
                              void* d_out, int out_size)
{
    const float* inputs = (const float*)d_in[0];  // [512,64,256]
    const float* spike0 = (const float*)d_in[1];  // [64,256]
    const float* v0     = (const float*)d_in[2];  // [64,256]
    const float* W_in   = (const float*)d_in[3];  // [256,256]
    const float* W_rec  = (const float*)d_in[4];  // [256,256]
    const float* W_out  = (const float*)d_in[5];  // [256,256]
    const float* bvec   = (const float*)d_in[6];  // [256]

    float* out = (float*)d_out;
    float* spikes = out;
    float* preds  = out + (size_t)513 * B_SZ * H_SZ;
    float* probs  = preds + (size_t)T_STEPS * B_SZ * H_SZ;
    float* vT     = probs + (size_t)T_STEPS * B_SZ * H_SZ;
    float* sT     = vT + (size_t)B_SZ * H_SZ;

    float* xw = nullptr;
    cudaGetSymbolAddress((void**)&xw, g_xw);
    int* stepcnt = nullptr;
    cudaGetSymbolAddress((void**)&stepcnt, g_stepcnt);

    cudaMemsetAsync(stepcnt, 0, T_STEPS * sizeof(int));

    const size_t smem = (size_t)SVEC * 512 * sizeof(ulonglong2)
                      + 2 * 256 * sizeof(float);              // 98 KB
    cudaFuncSetAttribute(mega_k, cudaFuncAttributeMaxDynamicSharedMemorySize,
                         (int)smem);

    dim3 gemm_grid((T_STEPS * B_SZ) / 128, H_SZ / 128);  // (256, 2)

    // 1) xw = inputs @ W_in + b (full chip)
    sgemm_k<<<gemm_grid, 256>>>(inputs, W_in, bvec, xw);

    // 2) scan + overlapped preds GEMM
    mega_k<<<N_SCAN_CTAS + N_HELPERS, 512, smem>>>(
        spike0, v0, W_rec, W_out, spikes, preds, probs, vT, sT, xw);
}

// round 17
// speedup vs baseline: 1.4603x; 1.4603x over previous
#include <cuda_runtime.h>
#include <cuda_bf16.h>
#include <cstdint>
#include <math.h>

// Problem dims (fixed by the dataset)
#define T_STEPS 512
#define B_SZ    64
#define D_SZ    256
#define H_SZ    256
#define ALPHA   0.9f

#define N_SCAN_CTAS   64
#define N_HELPERS     84
#define N_TILES       512   // preds: 256 bm x 2 bn, tiles of 128x128

__device__ float g_xw[(size_t)T_STEPS * B_SZ * H_SZ];
__device__ int   g_stepcnt[T_STEPS];   // #scan CTAs that completed step s (odd only)

// ---- f32x2 helpers (sm_103a packed fp32 FMA) --------------------------------
__device__ __forceinline__ unsigned long long pk2(float lo, float hi) {
    unsigned long long r;
    asm("mov.b64 %0, {%1, %2};" : "=l"(r) : "f"(lo), "f"(hi));
    return r;
}
__device__ __forceinline__ unsigned long long dup2(float a) {
    unsigned long long r;
    asm("mov.b64 %0, {%1, %1};" : "=l"(r) : "f"(a));
    return r;
}
__device__ __forceinline__ void fma2(unsigned long long& acc,
                                     unsigned long long a, unsigned long long b) {
    asm("fma.rn.f32x2 %0, %1, %2, %0;" : "+l"(acc) : "l"(a), "l"(b));
}
__device__ __forceinline__ float2 unpk(unsigned long long v) {
    float lo, hi;
    asm("mov.b64 {%0, %1}, %2;" : "=f"(lo), "=f"(hi) : "l"(v));
    return make_float2(lo, hi);
}

// ---- release/acquire flag ops ----------------------------------------------
__device__ __forceinline__ int ld_acq(const int* p) {
    int v;
    asm volatile("ld.acquire.gpu.global.s32 %0, [%1];" : "=r"(v) : "l"(p) : "memory");
    return v;
}
__device__ __forceinline__ void red_rel_add(int* p, int v) {
    asm volatile("red.release.gpu.global.add.s32 [%0], %1;" :: "l"(p), "r"(v) : "memory");
}

// ---------------------------------------------------------------------------
// One 128x128 GEMM tile body: C = A@Bm (+bias). BK=8, 256 threads, FFMA2.
// ---------------------------------------------------------------------------
__device__ __forceinline__ void gemm_tile(
    const float* __restrict__ A, const float* __restrict__ Bm,
    const float* __restrict__ bias, float* __restrict__ C,
    int bm, int bn, float* As, float* Bs)
{
    const int K = 256, N = 256;
    const int tid = threadIdx.x;
    const int tx = tid & 15;
    const int ty = tid >> 4;

    const int a_m = tid >> 1;
    const int a_k = (tid & 1) * 4;
    const int b_k = tid >> 5;
    const int b_n = (tid & 31) * 4;

    const float* Ap = A + (size_t)(bm + a_m) * K + a_k;
    const float* Bp = Bm + (size_t)b_k * N + bn + b_n;

    float4 af = *(const float4*)Ap;
    float4 bf = *(const float4*)Bp;

    unsigned long long acc2[8][4];
#pragma unroll
    for (int i = 0; i < 8; i++)
#pragma unroll
        for (int j = 0; j < 4; j++) acc2[i][j] = 0ull;

    int buf = 0;
    for (int kt = 0; kt < K; kt += 8) {
        As[(buf * 8 + a_k + 0) * 128 + a_m] = af.x;
        As[(buf * 8 + a_k + 1) * 128 + a_m] = af.y;
        As[(buf * 8 + a_k + 2) * 128 + a_m] = af.z;
        As[(buf * 8 + a_k + 3) * 128 + a_m] = af.w;
        *(float4*)&Bs[(buf * 8 + b_k) * 128 + b_n] = bf;
        __syncthreads();
        if (kt + 8 < K) {
            af = *(const float4*)(Ap + kt + 8);
            bf = *(const float4*)(Bp + (size_t)(kt + 8) * N);
        }
#pragma unroll
        for (int k = 0; k < 8; k++) {
            float4 a0 = *(const float4*)&As[(buf * 8 + k) * 128 + ty * 4];
            float4 a1 = *(const float4*)&As[(buf * 8 + k) * 128 + 64 + ty * 4];
            ulonglong2 bx0 = *(const ulonglong2*)&Bs[(buf * 8 + k) * 128 + tx * 4];
            ulonglong2 bx1 = *(const ulonglong2*)&Bs[(buf * 8 + k) * 128 + 64 + tx * 4];
            float av[8] = {a0.x, a0.y, a0.z, a0.w, a1.x, a1.y, a1.z, a1.w};
#pragma unroll
            for (int i = 0; i < 8; i++) {
                unsigned long long ad = dup2(av[i]);
                fma2(acc2[i][0], ad, bx0.x);
                fma2(acc2[i][1], ad, bx0.y);
                fma2(acc2[i][2], ad, bx1.x);
                fma2(acc2[i][3], ad, bx1.y);
            }
        }
        buf ^= 1;
    }

    float bv0[4], bv1[4];
#pragma unroll
    for (int j = 0; j < 4; j++) {
        bv0[j] = bias ? bias[bn + tx * 4 + j]      : 0.f;
        bv1[j] = bias ? bias[bn + 64 + tx * 4 + j] : 0.f;
    }

#pragma unroll
    for (int i = 0; i < 8; i++) {
        int r = bm + ((i < 4) ? (ty * 4 + i) : (64 + ty * 4 + (i - 4)));
        float2 p0 = unpk(acc2[i][0]), p1 = unpk(acc2[i][1]);
        float2 p2 = unpk(acc2[i][2]), p3 = unpk(acc2[i][3]);
        float4 o0, o1;
        o0.x = p0.x + bv0[0]; o0.y = p0.y + bv0[1];
        o0.z = p1.x + bv0[2]; o0.w = p1.y + bv0[3];
        o1.x = p2.x + bv1[0]; o1.y = p2.y + bv1[1];
        o1.z = p3.x + bv1[2]; o1.w = p3.y + bv1[3];
        *(float4*)&C[(size_t)r * N + bn + tx * 4]      = o0;
        *(float4*)&C[(size_t)r * N + bn + 64 + tx * 4] = o1;
    }
}

// Standalone full-chip GEMM for xw (proven config)
__global__ __launch_bounds__(256) void sgemm_k(
    const float* __restrict__ A, const float* __restrict__ Bm,
    const float* __restrict__ bias, float* __restrict__ C)
{
    __shared__ float As[2 * 8 * 128];
    __shared__ float Bs[2 * 8 * 128];
    gemm_tile(A, Bm, bias, C, blockIdx.x * 128, blockIdx.y * 128, As, Bs);
}

// ---------------------------------------------------------------------------
// Mega kernel: CTAs [0,64) = scan; CTAs [64,148) = preds helpers.
// Scan: W = 80 reg-pairs (rows 0..159) + 24 smem ulonglong2 vecs (rows
// 160..255). The register-part s-loads are software double-buffered in
// batches of 4 LDS.128 (MLP=4) to hide shared-memory latency.
// ---------------------------------------------------------------------------
#define WREG_PAIRS 80            // 160 W_rec rows in registers
#define WSM_VECS   24            // 96 rows in smem as ulonglong2 (4 rows/vec)
#define RBLK       (WREG_PAIRS / 8)   // 10 blocks of 4 s-vectors

__global__ __launch_bounds__(256, 1) void mega_k(
    const float* __restrict__ spike0, const float* __restrict__ v0,
    const float* __restrict__ W_rec,  const float* __restrict__ W_out,
    float* __restrict__ spikes, float* __restrict__ preds,
    float* __restrict__ probs,  float* __restrict__ vT, float* __restrict__ sT,
    const float* __restrict__ xw)
{
    extern __shared__ __align__(16) unsigned char dynsm[];

    if (blockIdx.x >= N_SCAN_CTAS) {
        // ================= preds helper =================
        float* As = (float*)dynsm;
        float* Bs = As + 2 * 8 * 128;
        const int h = blockIdx.x - N_SCAN_CTAS;
        const float* spk1 = spikes + (size_t)B_SZ * H_SZ;   // spikes[1:]

        for (int i = h; i < N_TILES; i += N_HELPERS) {
            const int bm = i >> 1, bn = i & 1;
            const int need_step = 2 * bm + 1;     // odd; published by scan
            if (threadIdx.x == 0) {
                while (ld_acq(&g_stepcnt[need_step]) < N_SCAN_CTAS)
                    __nanosleep(512);
            }
            __syncthreads();                      // acquire visible block-wide
            gemm_tile(spk1, W_out, nullptr, preds, bm * 128, bn * 128, As, Bs);
            __syncthreads();
        }
        return;
    }

    // ================= scan CTA =================
    ulonglong2* w4 = (ulonglong2*)dynsm;                     // [WSM_VECS*256]
    float* sbuf = (float*)(w4 + WSM_VECS * 256);             // [2][256]

    const int t   = threadIdx.x;   // output column
    const int row = blockIdx.x;    // batch row

    // Stage smem W vecs: vec q covers k rows 160+4q..163+4q, column t
#pragma unroll
    for (int q = 0; q < WSM_VECS; q++) {
        const int kb = 2 * WREG_PAIRS + 4 * q;
        ulonglong2 wv;
        wv.x = pk2(W_rec[(size_t)(kb + 0) * 256 + t], W_rec[(size_t)(kb + 1) * 256 + t]);
        wv.y = pk2(W_rec[(size_t)(kb + 2) * 256 + t], W_rec[(size_t)(kb + 3) * 256 + t]);
        w4[q * 256 + t] = wv;
    }

    // Register-resident W pairs: rows [0,160)
    unsigned long long wpk[WREG_PAIRS];
#pragma unroll
    for (int j = 0; j < WREG_PAIRS; j++)
        wpk[j] = pk2(W_rec[(size_t)(2 * j) * 256 + t],
                     W_rec[(size_t)(2 * j + 1) * 256 + t]);

    const float s0 = spike0[row * 256 + t];
    sbuf[t] = s0;
    spikes[(size_t)row * 256 + t] = s0;          // spikes[0] = spike0
    float v = v0[row * 256 + t];
    float prob = s0;

    const float* xwp = xw + (size_t)row * 256 + t;
    float xnext = __ldg(xwp);

    __syncthreads();

    int cur = 0;
    for (int step = 0; step < T_STEPS; step++) {
        const float xval = xnext;
        if (step + 1 < T_STEPS)
            xnext = __ldg(xwp + (size_t)(step + 1) * (B_SZ * H_SZ));

        unsigned long long a4[4] = {0ull, 0ull, 0ull, 0ull};
        const ulonglong2* sp = (const ulonglong2*)&sbuf[cur * 256];  // 64 vecs

        // -------- register part: s-vecs [0,40), double-buffered MLP=4 ------
        ulonglong2 b0[4], b1[4];
#pragma unroll
        for (int i = 0; i < 4; i++) b0[i] = sp[i];
#pragma unroll
        for (int blk = 0; blk < RBLK; blk++) {
            ulonglong2* curb = (blk & 1) ? b1 : b0;
            ulonglong2* nxtb = (blk & 1) ? b0 : b1;
            if (blk + 1 < RBLK) {
#pragma unroll
                for (int i = 0; i < 4; i++) nxtb[i] = sp[4 * (blk + 1) + i];
            }
#pragma unroll
            for (int i = 0; i < 4; i++) {
                const int q = 4 * blk + i;      // s-vec index = W pair-pair idx
                fma2(a4[(2 * i) & 3],     wpk[2 * q],     curb[i].x);
                fma2(a4[(2 * i + 1) & 3], wpk[2 * q + 1], curb[i].y);
            }
        }

        // -------- smem part: s-vecs [40,64) with smem W vecs [0,24) --------
#pragma unroll
        for (int q = 0; q < WSM_VECS; q++) {
            ulonglong2 sv = sp[WREG_PAIRS / 2 + q];
            ulonglong2 wv = w4[q * 256 + t];
            fma2(a4[0], wv.x, sv.x);
            fma2(a4[1], wv.y, sv.y);
        }

        float2 q0 = unpk(a4[0]), q1 = unpk(a4[1]), q2 = unpk(a4[2]), q3 = unpk(a4[3]);
        float acc = ((q0.x + q0.y) + (q1.x + q1.y)) + ((q2.x + q2.y) + (q3.x + q3.y));

        v = ALPHA * v + xval + acc;
        prob = __fdividef(1.0f, 1.0f + __expf(-v));

        const size_t off = ((size_t)step * B_SZ + row) * 256 + t;
        probs[off] = prob;                        // probs[step]
        spikes[off + (size_t)B_SZ * 256] = prob;  // spikes[step+1]

        const int nxt = cur ^ 1;
        sbuf[nxt * 256 + t] = prob;
        __syncthreads();   // all lanes' STGs ordered before publish (HB chain)
        if (t == 0 && (step & 1)) red_rel_add(&g_stepcnt[step], 1);
        cur = nxt;
    }

    vT[row * 256 + t] = v;
    sT[row * 256 + t] = prob;
}

// ---------------------------------------------------------------------------
// Launch: memset flags -> sgemm(xw) -> mega(scan + preds helpers).
// ---------------------------------------------------------------------------
extern "C" void kernel_launch(void* const* d_in, const int* in_sizes, int n_in,
                              void* d_out, int out_size)
{
    const float* inputs = (const float*)d_in[0];  // [512,64,256]
    const float* spike0 = (const float*)d_in[1];  // [64,256]
    const float* v0     = (const float*)d_in[2];  // [64,256]
    const float* W_in   = (const float*)d_in[3];  // [256,256]
    const float* W_rec  = (const float*)d_in[4];  // [256,256]
    const float* W_out  = (const float*)d_in[5];  // [256,256]
    const float* bvec   = (const float*)d_in[6];  // [256]

    float* out = (float*)d_out;
    float* spikes = out;
    float* preds  = out + (size_t)513 * B_SZ * H_SZ;
    float* probs  = preds + (size_t)T_STEPS * B_SZ * H_SZ;
    float* vT     = probs + (size_t)T_STEPS * B_SZ * H_SZ;
    float* sT     = vT + (size_t)B_SZ * H_SZ;

    float* xw = nullptr;
    cudaGetSymbolAddress((void**)&xw, g_xw);
    int* stepcnt = nullptr;
    cudaGetSymbolAddress((void**)&stepcnt, g_stepcnt);

    cudaMemsetAsync(stepcnt, 0, T_STEPS * sizeof(int));

    const size_t smem = (size_t)WSM_VECS * 256 * sizeof(ulonglong2)
                      + 2 * 256 * sizeof(float);              // ~98 KB
    cudaFuncSetAttribute(mega_k, cudaFuncAttributeMaxDynamicSharedMemorySize,
                         (int)smem);

    dim3 gemm_grid((T_STEPS * B_SZ) / 128, H_SZ / 128);  // (256, 2)

    // 1) xw = inputs @ W_in + b (full chip)
    sgemm_k<<<gemm_grid, 256>>>(inputs, W_in, bvec, xw);

    // 2) scan + overlapped preds GEMM
    mega_k<<<N_SCAN_CTAS + N_HELPERS, 256, smem>>>(
        spike0, v0, W_rec, W_out, spikes, preds, probs, vT, sT, xw);
}